// round 3
// baseline (speedup 1.0000x reference)
#include <cuda_runtime.h>

// Problem constants (match reference setup_inputs)
#define BQ 8
#define CC 64
#define HH 512
#define WW 512
#define OO 64
#define SS 4
// hs = ws = 128; elements per pooled tile = 128*128 = 16384

// Scratch (allocation-free rule: __device__ global). Only 8 KB.
__device__ float g_pooled[BQ * CC * SS * SS];    // [b, c, i, j]

// ---------------------------------------------------------------------------
// Kernel 1: segment mean-pool.
// Grid: BQ*CC*SS = 2048 CTAs; each CTA handles one (b, c, i) stripe
// = 128 rows x 512 cols. 256 threads, streaming float4 loads (__ldcs:
// zero reuse, keep it out of L2's working set). Thread's column (idx & 127)
// is invariant under the +=256 stride, so each warp sees exactly one j.
// ---------------------------------------------------------------------------
__global__ __launch_bounds__(256) void pool_kernel(const float* __restrict__ x) {
    int bi = blockIdx.x;             // b*CC*SS + c*SS + i
    int i  = bi % SS;
    int c  = (bi / SS) % CC;
    int b  = bi / (SS * CC);

    const float4* base = reinterpret_cast<const float4*>(
        x + (((size_t)(b * CC + c)) * HH + (size_t)i * 128) * WW);

    int tid = threadIdx.x;
    float s0 = 0.0f, s1 = 0.0f;
    // 128 rows * 128 float4/row = 16384 float4 per stripe; 2 accumulators
    // for ILP, 8-deep unroll for MLP.
    #pragma unroll 8
    for (int idx = tid; idx < 128 * 128; idx += 512) {
        float4 a = __ldcs(&base[idx]);
        float4 c4 = __ldcs(&base[idx + 256]);
        s0 += (a.x + a.y) + (a.z + a.w);
        s1 += (c4.x + c4.y) + (c4.z + c4.w);
    }
    float sum = s0 + s1;

    // warp reduce (all lanes in a warp share the same j)
    #pragma unroll
    for (int off = 16; off; off >>= 1)
        sum += __shfl_down_sync(0xffffffffu, sum, off);

    __shared__ float sj[SS];
    if (tid < SS) sj[tid] = 0.0f;
    __syncthreads();

    int wid = tid >> 5;
    int j   = wid & 3;               // warps 0-3 -> j 0-3, warps 4-7 -> j 0-3
    if ((tid & 31) == 0) atomicAdd(&sj[j], sum);
    __syncthreads();

    if (tid < SS)
        g_pooled[((size_t)(b * CC + c) * SS + i) * SS + tid] =
            sj[tid] * (1.0f / 16384.0f);
}

// ---------------------------------------------------------------------------
// Kernel 2 (fused mix + broadcast): one CTA per (b, o, i) stripe.
// Head: cooperative 64-wide dot for the 4 j-values of this stripe
//   (pooled + W live in L2 — 8 KB + 16 KB — so this costs ~600 cycles,
//    hidden by other CTAs' store streams).
// Body: stream 128 rows x 512 cols of broadcast values with __stcs
//   (write-once data: evict-first, don't pollute L2).
// ---------------------------------------------------------------------------
__global__ __launch_bounds__(256) void bcast_kernel(float4* __restrict__ out,
                                                    const float* __restrict__ Wm,
                                                    const float* __restrict__ bias,
                                                    const float* __restrict__ seg_w) {
    int blk = blockIdx.x;            // (b*OO + o)*SS + i
    int i   = blk & 3;
    int p   = blk >> 2;              // plane index b*OO + o
    int o   = p & (OO - 1);
    int b   = p >> 6;

    int tid = threadIdx.x;

    // --- cooperative dot: 4 groups of 64 threads, group g handles j=g ---
    int jg = tid >> 6;               // 0..3
    int c  = tid & 63;               // 0..63
    float part = g_pooled[((size_t)(b * CC + c) * SS + i) * SS + jg] *
                 __ldg(&Wm[(size_t)o * CC + c]);
    #pragma unroll
    for (int off = 16; off; off >>= 1)
        part += __shfl_down_sync(0xffffffffu, part, off);

    __shared__ float partial[8];     // one per warp
    if ((tid & 31) == 0) partial[tid >> 5] = part;
    __syncthreads();

    __shared__ float wv[SS];
    if (tid < SS)
        wv[tid] = (partial[2 * tid] + partial[2 * tid + 1] + __ldg(&bias[o])) *
                  __ldg(&seg_w[i * SS + tid]);
    __syncthreads();

    // --- broadcast stream: 128 rows x 128 float4 = 16384 f4 per CTA ---
    int j = (tid & 127) >> 5;        // column segment, constant per thread
    float v = wv[j];
    float4 v4 = make_float4(v, v, v, v);

    float4* dst = out + ((size_t)p * HH + (size_t)i * 128) * (WW / 4) + tid;
    #pragma unroll 8
    for (int k = 0; k < 64; k++)
        __stcs(&dst[(size_t)k * 256], v4);
}

// ---------------------------------------------------------------------------
extern "C" void kernel_launch(void* const* d_in, const int* in_sizes, int n_in,
                              void* d_out, int out_size) {
    const float* x     = (const float*)d_in[0];   // [B, C, H, W]
    const float* Wm    = (const float*)d_in[1];   // [O, C]
    const float* bias  = (const float*)d_in[2];   // [O]
    const float* seg_w = (const float*)d_in[3];   // [S, S]
    float* out = (float*)d_out;                   // [B, O, H, W]

    pool_kernel<<<BQ * CC * SS, 256>>>(x);
    bcast_kernel<<<BQ * OO * SS, 256>>>((float4*)out, Wm, bias, seg_w);
}